// round 10
// baseline (speedup 1.0000x reference)
#include <cuda_runtime.h>

#define NN 100000
#define NE 640000
#define F  128
#define G  64
#define BN_EPS 1e-5f

// ---------------- scratch (device globals: no allocations allowed) ----------
__device__ float g_h[(size_t)NN * F];      // (x @ W_gcn) * dinv[row]  (pre-scaled)
__device__ float g_agg[(size_t)NN * F];    // aggregated + b_gcn (pre-BN1)
__device__ float g_t1[(size_t)NN * G];     // relu(bn1(agg)) @ W1 + b1 (pre-BN2)
__device__ int   g_cnt[NN];                // in-degree excluding self loop
__device__ float g_dinv[NN];               // 1/sqrt(deg+1)
__device__ int   g_rowstart[NN];           // CSR row offsets (exclusive scan of cnt)
__device__ int   g_cursor[NN];
__device__ int   g_src_sorted[NE];         // src ids bucketed by dst
__device__ float g_cs1[F], g_cq1[F];       // BN1 column sum / sumsq
__device__ float g_cs2[G], g_cq2[G];       // BN2 column sum / sumsq
__device__ int   g_bsums[256];             // scan block sums

// ---------------- init ------------------------------------------------------
__global__ void k_init() {
    int i = blockIdx.x * blockDim.x + threadIdx.x;
    if (i < NN) g_cnt[i] = 0;
    if (i < F) { g_cs1[i] = 0.f; g_cq1[i] = 0.f; }
    if (i < G) { g_cs2[i] = 0.f; g_cq2[i] = 0.f; }
}

// ---------------- degree count ----------------------------------------------
__global__ void k_count(const int* __restrict__ ei) {
    int e = blockIdx.x * blockDim.x + threadIdx.x;
    if (e < NE) atomicAdd(&g_cnt[ei[NE + e]], 1);
}

// ---------------- 3-kernel exclusive scan of g_cnt -> g_rowstart ------------
#define SCAN_B 512
__global__ void k_scan1() {
    __shared__ int s[SCAN_B];
    int i = blockIdx.x * SCAN_B + threadIdx.x;
    int v = (i < NN) ? g_cnt[i] : 0;
    s[threadIdx.x] = v;
    __syncthreads();
    for (int off = 1; off < SCAN_B; off <<= 1) {
        int t = 0;
        if (threadIdx.x >= off) t = s[threadIdx.x - off];
        __syncthreads();
        if (threadIdx.x >= off) s[threadIdx.x] += t;
        __syncthreads();
    }
    if (i < NN) g_rowstart[i] = s[threadIdx.x] - v;   // exclusive
    if (threadIdx.x == SCAN_B - 1) g_bsums[blockIdx.x] = s[SCAN_B - 1];
}

__global__ void k_scan2(int nblk) {
    __shared__ int s[256];
    int v = (threadIdx.x < nblk) ? g_bsums[threadIdx.x] : 0;
    s[threadIdx.x] = v;
    __syncthreads();
    for (int off = 1; off < 256; off <<= 1) {
        int t = 0;
        if (threadIdx.x >= off) t = s[threadIdx.x - off];
        __syncthreads();
        if (threadIdx.x >= off) s[threadIdx.x] += t;
        __syncthreads();
    }
    if (threadIdx.x < nblk) g_bsums[threadIdx.x] = s[threadIdx.x] - v;  // exclusive
}

__global__ void k_scan3() {
    int i = blockIdx.x * blockDim.x + threadIdx.x;
    if (i < NN) {
        int rs = g_rowstart[i] + g_bsums[i >> 9];
        g_rowstart[i] = rs;
        g_cursor[i]   = rs;
        g_dinv[i]     = rsqrtf((float)(g_cnt[i] + 1));  // +1 self loop
    }
}

// ---------------- bucket edges by dst ---------------------------------------
__global__ void k_bucket(const int* __restrict__ ei) {
    int e = blockIdx.x * blockDim.x + threadIdx.x;
    if (e < NE) {
        int d = ei[NE + e];
        int p = atomicAdd(&g_cursor[d], 1);
        g_src_sorted[p] = ei[e];
    }
}

// ---------------- GEMM1: g_h = (x @ W_gcn) * dinv[row] ----------------------
// BM=64 rows/block, full K=128 and N=128 in smem. 256 thr, micro-tile 4x8.
// Epilogue pre-scales each output row by dinv[row] so the aggregation loop
// needs no per-edge normalization loads/multiplies.
__global__ void __launch_bounds__(256) k_gemm1(const float* __restrict__ x,
                                               const float* __restrict__ Wg) {
    extern __shared__ float sm[];
    float* As = sm;                 // 64*128
    float* Ws = sm + 64 * F;        // 128*128
    int tid = threadIdx.x;
    // load W (16384 floats = 4096 float4)
    #pragma unroll
    for (int it = 0; it < 16; it++) {
        int idx = it * 256 + tid;
        ((float4*)Ws)[idx] = ((const float4*)Wg)[idx];
    }
    int row0 = blockIdx.x * 64;
    // load A tile (64x128 = 2048 float4)
    #pragma unroll
    for (int it = 0; it < 8; it++) {
        int idx = it * 256 + tid;
        int r = idx >> 5, c4 = idx & 31;
        float4 v = make_float4(0.f, 0.f, 0.f, 0.f);
        if (row0 + r < NN) v = ((const float4*)(x + (size_t)(row0 + r) * F))[c4];
        ((float4*)(As + r * F))[c4] = v;
    }
    __syncthreads();

    int ty = tid >> 4, tx = tid & 15;
    float acc[4][8];
    #pragma unroll
    for (int i = 0; i < 4; i++)
        #pragma unroll
        for (int j = 0; j < 8; j++) acc[i][j] = 0.f;

    #pragma unroll 4
    for (int k = 0; k < F; k++) {
        float a[4];
        #pragma unroll
        for (int i = 0; i < 4; i++) a[i] = As[(ty * 4 + i) * F + k];
        float4 b0 = *(const float4*)&Ws[k * F + tx * 4];
        float4 b1 = *(const float4*)&Ws[k * F + 64 + tx * 4];
        #pragma unroll
        for (int i = 0; i < 4; i++) {
            acc[i][0] += a[i] * b0.x; acc[i][1] += a[i] * b0.y;
            acc[i][2] += a[i] * b0.z; acc[i][3] += a[i] * b0.w;
            acc[i][4] += a[i] * b1.x; acc[i][5] += a[i] * b1.y;
            acc[i][6] += a[i] * b1.z; acc[i][7] += a[i] * b1.w;
        }
    }
    #pragma unroll
    for (int i = 0; i < 4; i++) {
        int r = row0 + ty * 4 + i;
        if (r < NN) {
            float di = g_dinv[r];
            float4 v0 = make_float4(acc[i][0] * di, acc[i][1] * di,
                                    acc[i][2] * di, acc[i][3] * di);
            float4 v1 = make_float4(acc[i][4] * di, acc[i][5] * di,
                                    acc[i][6] * di, acc[i][7] * di);
            *(float4*)&g_h[(size_t)r * F + tx * 4]      = v0;
            *(float4*)&g_h[(size_t)r * F + 64 + tx * 4] = v1;
        }
    }
}

// ---------------- aggregation (gather-only, warp per node) + BN1 stats ------
// g_h rows are pre-scaled by dinv[src]; the loop is a pure sum of rows.
// 4-wide unroll keeps ~8 lines in flight per lane to hide L2-hit latency.
__global__ void __launch_bounds__(256) k_agg(const float* __restrict__ bgcn) {
    __shared__ float ss[8][F];
    __shared__ float sq[8][F];
    int w = threadIdx.x >> 5, lane = threadIdx.x & 31;
    int node = blockIdx.x * 8 + w;          // 12500 blocks * 8 == NN exactly

    float di = g_dinv[node];
    // self-loop term: h_scaled[node] (already carries dinv[node])
    float4 acc = ((const float4*)(g_h + (size_t)node * F))[lane];

    int rs = g_rowstart[node];
    int cn = g_cnt[node];
    int t = 0;
    for (; t + 4 <= cn; t += 4) {
        int s0 = g_src_sorted[rs + t];
        int s1 = g_src_sorted[rs + t + 1];
        int s2 = g_src_sorted[rs + t + 2];
        int s3 = g_src_sorted[rs + t + 3];
        float4 v0 = ((const float4*)(g_h + (size_t)s0 * F))[lane];
        float4 v1 = ((const float4*)(g_h + (size_t)s1 * F))[lane];
        float4 v2 = ((const float4*)(g_h + (size_t)s2 * F))[lane];
        float4 v3 = ((const float4*)(g_h + (size_t)s3 * F))[lane];
        acc.x += v0.x + v1.x + v2.x + v3.x;
        acc.y += v0.y + v1.y + v2.y + v3.y;
        acc.z += v0.z + v1.z + v2.z + v3.z;
        acc.w += v0.w + v1.w + v2.w + v3.w;
    }
    for (; t < cn; t++) {
        int s = g_src_sorted[rs + t];
        float4 v = ((const float4*)(g_h + (size_t)s * F))[lane];
        acc.x += v.x; acc.y += v.y; acc.z += v.z; acc.w += v.w;
    }
    // final dst-side scale + bias
    float4 bb = ((const float4*)bgcn)[lane];
    acc.x = fmaf(di, acc.x, bb.x);
    acc.y = fmaf(di, acc.y, bb.y);
    acc.z = fmaf(di, acc.z, bb.z);
    acc.w = fmaf(di, acc.w, bb.w);
    ((float4*)(g_agg + (size_t)node * F))[lane] = acc;

    int c = lane * 4;
    ss[w][c] = acc.x; ss[w][c + 1] = acc.y; ss[w][c + 2] = acc.z; ss[w][c + 3] = acc.w;
    sq[w][c] = acc.x * acc.x; sq[w][c + 1] = acc.y * acc.y;
    sq[w][c + 2] = acc.z * acc.z; sq[w][c + 3] = acc.w * acc.w;
    __syncthreads();
    if (threadIdx.x < F) {
        float s = 0.f, q = 0.f;
        #pragma unroll
        for (int i = 0; i < 8; i++) { s += ss[i][threadIdx.x]; q += sq[i][threadIdx.x]; }
        atomicAdd(&g_cs1[threadIdx.x], s);
        atomicAdd(&g_cq1[threadIdx.x], q);
    }
}

// ---- GEMM2: t1 = relu(bn1(agg)) @ W1 + b1, fused BN2 stats -----------------
// BM=64, K=128, N=64. 256 thr, micro 4x4.
__global__ void __launch_bounds__(256) k_gemm2(const float* __restrict__ gamma,
                                               const float* __restrict__ beta,
                                               const float* __restrict__ W1,
                                               const float* __restrict__ b1) {
    extern __shared__ float sm[];
    float* As = sm;                // 64*128
    float* Ws = As + 64 * F;       // 128*64
    float* sc = Ws + F * G;        // 128
    float* sh = sc + F;            // 128
    int tid = threadIdx.x;

    if (tid < F) {
        float mean = g_cs1[tid] * (1.f / NN);
        float var  = g_cq1[tid] * (1.f / NN) - mean * mean;
        float r    = rsqrtf(var + BN_EPS);
        float s    = r * gamma[tid];
        sc[tid] = s;
        sh[tid] = beta[tid] - mean * s;
    }
    // load W1 (8192 floats = 2048 float4)
    #pragma unroll
    for (int it = 0; it < 8; it++) {
        int idx = it * 256 + tid;
        ((float4*)Ws)[idx] = ((const float4*)W1)[idx];
    }
    __syncthreads();

    int row0 = blockIdx.x * 64;
    // load + normalize + relu A tile (64x128 = 2048 float4)
    #pragma unroll
    for (int it = 0; it < 8; it++) {
        int idx = it * 256 + tid;
        int r = idx >> 5, c4 = idx & 31;
        float4 v = make_float4(0.f, 0.f, 0.f, 0.f);
        if (row0 + r < NN) {
            float4 a = ((const float4*)(g_agg + (size_t)(row0 + r) * F))[c4];
            int c = c4 * 4;
            v.x = fmaxf(0.f, fmaf(a.x, sc[c],     sh[c]));
            v.y = fmaxf(0.f, fmaf(a.y, sc[c + 1], sh[c + 1]));
            v.z = fmaxf(0.f, fmaf(a.z, sc[c + 2], sh[c + 2]));
            v.w = fmaxf(0.f, fmaf(a.w, sc[c + 3], sh[c + 3]));
        }
        ((float4*)(As + r * F))[c4] = v;
    }
    __syncthreads();

    int ty = tid >> 4, tx = tid & 15;
    float acc[4][4];
    #pragma unroll
    for (int i = 0; i < 4; i++)
        #pragma unroll
        for (int j = 0; j < 4; j++) acc[i][j] = 0.f;

    #pragma unroll 4
    for (int k = 0; k < F; k++) {
        float a[4];
        #pragma unroll
        for (int i = 0; i < 4; i++) a[i] = As[(ty * 4 + i) * F + k];
        float4 b = *(const float4*)&Ws[k * G + tx * 4];
        #pragma unroll
        for (int i = 0; i < 4; i++) {
            acc[i][0] += a[i] * b.x; acc[i][1] += a[i] * b.y;
            acc[i][2] += a[i] * b.z; acc[i][3] += a[i] * b.w;
        }
    }

    float4 bb = ((const float4*)b1)[tx];
    float ps[4] = {0.f, 0.f, 0.f, 0.f};
    float pq[4] = {0.f, 0.f, 0.f, 0.f};
    #pragma unroll
    for (int i = 0; i < 4; i++) {
        int r = row0 + ty * 4 + i;
        if (r < NN) {
            float4 v;
            v.x = acc[i][0] + bb.x; v.y = acc[i][1] + bb.y;
            v.z = acc[i][2] + bb.z; v.w = acc[i][3] + bb.w;
            *(float4*)&g_t1[(size_t)r * G + tx * 4] = v;
            ps[0] += v.x; ps[1] += v.y; ps[2] += v.z; ps[3] += v.w;
            pq[0] += v.x * v.x; pq[1] += v.y * v.y;
            pq[2] += v.z * v.z; pq[3] += v.w * v.w;
        }
    }
    // block-reduce BN2 stats (reuse smem)
    __syncthreads();
    float* red = sm;               // 16*64
    #pragma unroll
    for (int j = 0; j < 4; j++) red[ty * G + tx * 4 + j] = ps[j];
    __syncthreads();
    if (tid < G) {
        float s = 0.f;
        #pragma unroll
        for (int i = 0; i < 16; i++) s += red[i * G + tid];
        atomicAdd(&g_cs2[tid], s);
    }
    __syncthreads();
    #pragma unroll
    for (int j = 0; j < 4; j++) red[ty * G + tx * 4 + j] = pq[j];
    __syncthreads();
    if (tid < G) {
        float q = 0.f;
        #pragma unroll
        for (int i = 0; i < 16; i++) q += red[i * G + tid];
        atomicAdd(&g_cq2[tid], q);
    }
}

// ---- GEMM3: out = relu(bn2(t1)) @ W2 + b2 ----------------------------------
__global__ void __launch_bounds__(256) k_gemm3(const float* __restrict__ gamma,
                                               const float* __restrict__ beta,
                                               const float* __restrict__ W2,
                                               const float* __restrict__ b2,
                                               float* __restrict__ out) {
    __shared__ float As[64 * G];
    __shared__ float Ws[G * G];
    __shared__ float sc[G];
    __shared__ float sh[G];
    int tid = threadIdx.x;

    if (tid < G) {
        float mean = g_cs2[tid] * (1.f / NN);
        float var  = g_cq2[tid] * (1.f / NN) - mean * mean;
        float r    = rsqrtf(var + BN_EPS);
        float s    = r * gamma[tid];
        sc[tid] = s;
        sh[tid] = beta[tid] - mean * s;
    }
    // load W2 (4096 floats = 1024 float4)
    #pragma unroll
    for (int it = 0; it < 4; it++) {
        int idx = it * 256 + tid;
        ((float4*)Ws)[idx] = ((const float4*)W2)[idx];
    }
    __syncthreads();

    int row0 = blockIdx.x * 64;
    #pragma unroll
    for (int it = 0; it < 4; it++) {
        int idx = it * 256 + tid;
        int r = idx >> 4, c4 = idx & 15;
        float4 v = make_float4(0.f, 0.f, 0.f, 0.f);
        if (row0 + r < NN) {
            float4 a = ((const float4*)(g_t1 + (size_t)(row0 + r) * G))[c4];
            int c = c4 * 4;
            v.x = fmaxf(0.f, fmaf(a.x, sc[c],     sh[c]));
            v.y = fmaxf(0.f, fmaf(a.y, sc[c + 1], sh[c + 1]));
            v.z = fmaxf(0.f, fmaf(a.z, sc[c + 2], sh[c + 2]));
            v.w = fmaxf(0.f, fmaf(a.w, sc[c + 3], sh[c + 3]));
        }
        ((float4*)(As + r * G))[c4] = v;
    }
    __syncthreads();

    int ty = tid >> 4, tx = tid & 15;
    float acc[4][4];
    #pragma unroll
    for (int i = 0; i < 4; i++)
        #pragma unroll
        for (int j = 0; j < 4; j++) acc[i][j] = 0.f;

    #pragma unroll 4
    for (int k = 0; k < G; k++) {
        float a[4];
        #pragma unroll
        for (int i = 0; i < 4; i++) a[i] = As[(ty * 4 + i) * G + k];
        float4 b = *(const float4*)&Ws[k * G + tx * 4];
        #pragma unroll
        for (int i = 0; i < 4; i++) {
            acc[i][0] += a[i] * b.x; acc[i][1] += a[i] * b.y;
            acc[i][2] += a[i] * b.z; acc[i][3] += a[i] * b.w;
        }
    }

    float4 bb = ((const float4*)b2)[tx];
    #pragma unroll
    for (int i = 0; i < 4; i++) {
        int r = row0 + ty * 4 + i;
        if (r < NN) {
            float4 v;
            v.x = acc[i][0] + bb.x; v.y = acc[i][1] + bb.y;
            v.z = acc[i][2] + bb.z; v.w = acc[i][3] + bb.w;
            *(float4*)&out[(size_t)r * G + tx * 4] = v;
        }
    }
}

// ---------------- host ------------------------------------------------------
extern "C" void kernel_launch(void* const* d_in, const int* in_sizes, int n_in,
                              void* d_out, int out_size) {
    const float* x   = (const float*)d_in[0];
    const int*   ei  = (const int*)  d_in[1];
    const float* Wg  = (const float*)d_in[2];
    const float* bg  = (const float*)d_in[3];
    const float* g1  = (const float*)d_in[4];
    const float* be1 = (const float*)d_in[5];
    const float* W1  = (const float*)d_in[6];
    const float* b1  = (const float*)d_in[7];
    const float* g2  = (const float*)d_in[8];
    const float* be2 = (const float*)d_in[9];
    const float* W2  = (const float*)d_in[10];
    const float* b2  = (const float*)d_in[11];
    float* out = (float*)d_out;

    // opt-in dynamic smem (>48KB); host-side attribute set, graph-capture safe
    cudaFuncSetAttribute(k_gemm1, cudaFuncAttributeMaxDynamicSharedMemorySize,
                         (64 * F + F * F) * (int)sizeof(float));
    cudaFuncSetAttribute(k_gemm2, cudaFuncAttributeMaxDynamicSharedMemorySize,
                         (64 * F + F * G + 2 * F) * (int)sizeof(float));

    int nblk_scan = (NN + SCAN_B - 1) / SCAN_B;   // 196
    int gemm_blocks = (NN + 63) / 64;             // 1563

    k_init  <<<(NN + 255) / 256, 256>>>();
    k_count <<<(NE + 255) / 256, 256>>>(ei);
    k_scan1 <<<nblk_scan, SCAN_B>>>();
    k_scan2 <<<1, 256>>>(nblk_scan);
    k_scan3 <<<(NN + 255) / 256, 256>>>();
    k_bucket<<<(NE + 255) / 256, 256>>>(ei);
    k_gemm1 <<<gemm_blocks, 256, (64 * F + F * F) * sizeof(float)>>>(x, Wg);
    k_agg   <<<NN / 8, 256>>>(bg);
    k_gemm2 <<<gemm_blocks, 256, (64 * F + F * G + 2 * F) * sizeof(float)>>>(g1, be1, W1, b1);
    k_gemm3 <<<gemm_blocks, 256>>>(g2, be2, W2, b2, out);
}

// round 14
// speedup vs baseline: 1.0300x; 1.0300x over previous
#include <cuda_runtime.h>

#define NN 100000
#define NE 640000
#define F  128
#define G  64
#define BN_EPS 1e-5f

typedef unsigned long long u64;

// packed dual-fp32 helpers (sm_103a f32x2 pipe; bit-identical to scalar FFMA)
__device__ __forceinline__ u64 pack2(float lo, float hi) {
    u64 r; asm("mov.b64 %0, {%1,%2};" : "=l"(r) : "f"(lo), "f"(hi)); return r;
}
__device__ __forceinline__ void unpack2(u64 v, float& lo, float& hi) {
    asm("mov.b64 {%0,%1}, %2;" : "=f"(lo), "=f"(hi) : "l"(v));
}
__device__ __forceinline__ u64 ffma2(u64 a, u64 b, u64 c) {
    u64 d; asm("fma.rn.f32x2 %0, %1, %2, %3;" : "=l"(d) : "l"(a), "l"(b), "l"(c)); return d;
}
__device__ __forceinline__ u64 fmul2(u64 a, u64 b) {
    u64 d; asm("mul.rn.f32x2 %0, %1, %2;" : "=l"(d) : "l"(a), "l"(b)); return d;
}
__device__ __forceinline__ u64 fadd2(u64 a, u64 b) {
    u64 d; asm("add.rn.f32x2 %0, %1, %2;" : "=l"(d) : "l"(a), "l"(b)); return d;
}

// ---------------- scratch (device globals: no allocations allowed) ----------
__device__ float g_h[(size_t)NN * F];      // (x @ W_gcn) * dinv[row]  (pre-scaled)
__device__ float g_agg[(size_t)NN * F];    // aggregated + b_gcn (pre-BN1)
__device__ float g_t1[(size_t)NN * G];     // relu(bn1(agg)) @ W1 + b1 (pre-BN2)
__device__ int   g_cnt[NN];                // in-degree excluding self loop
__device__ float g_dinv[NN];               // 1/sqrt(deg+1)
__device__ int   g_rowstart[NN];           // CSR row offsets (exclusive scan of cnt)
__device__ int   g_cursor[NN];
__device__ int   g_src_sorted[NE];         // src ids bucketed by dst
__device__ float g_cs1[F], g_cq1[F];       // BN1 column sum / sumsq
__device__ float g_cs2[G], g_cq2[G];       // BN2 column sum / sumsq
__device__ int   g_bsums[256];             // scan block sums

// ---------------- init ------------------------------------------------------
__global__ void k_init() {
    int i = blockIdx.x * blockDim.x + threadIdx.x;
    if (i < NN) g_cnt[i] = 0;
    if (i < F) { g_cs1[i] = 0.f; g_cq1[i] = 0.f; }
    if (i < G) { g_cs2[i] = 0.f; g_cq2[i] = 0.f; }
}

// ---------------- degree count ----------------------------------------------
__global__ void k_count(const int* __restrict__ ei) {
    int e = blockIdx.x * blockDim.x + threadIdx.x;
    if (e < NE) atomicAdd(&g_cnt[ei[NE + e]], 1);
}

// ---------------- 3-kernel exclusive scan of g_cnt -> g_rowstart ------------
#define SCAN_B 512
__global__ void k_scan1() {
    __shared__ int s[SCAN_B];
    int i = blockIdx.x * SCAN_B + threadIdx.x;
    int v = (i < NN) ? g_cnt[i] : 0;
    s[threadIdx.x] = v;
    __syncthreads();
    for (int off = 1; off < SCAN_B; off <<= 1) {
        int t = 0;
        if (threadIdx.x >= off) t = s[threadIdx.x - off];
        __syncthreads();
        if (threadIdx.x >= off) s[threadIdx.x] += t;
        __syncthreads();
    }
    if (i < NN) g_rowstart[i] = s[threadIdx.x] - v;   // exclusive
    if (threadIdx.x == SCAN_B - 1) g_bsums[blockIdx.x] = s[SCAN_B - 1];
}

__global__ void k_scan2(int nblk) {
    __shared__ int s[256];
    int v = (threadIdx.x < nblk) ? g_bsums[threadIdx.x] : 0;
    s[threadIdx.x] = v;
    __syncthreads();
    for (int off = 1; off < 256; off <<= 1) {
        int t = 0;
        if (threadIdx.x >= off) t = s[threadIdx.x - off];
        __syncthreads();
        if (threadIdx.x >= off) s[threadIdx.x] += t;
        __syncthreads();
    }
    if (threadIdx.x < nblk) g_bsums[threadIdx.x] = s[threadIdx.x] - v;  // exclusive
}

__global__ void k_scan3() {
    int i = blockIdx.x * blockDim.x + threadIdx.x;
    if (i < NN) {
        int rs = g_rowstart[i] + g_bsums[i >> 9];
        g_rowstart[i] = rs;
        g_cursor[i]   = rs;
        g_dinv[i]     = rsqrtf((float)(g_cnt[i] + 1));  // +1 self loop
    }
}

// ---------------- bucket edges by dst ---------------------------------------
__global__ void k_bucket(const int* __restrict__ ei) {
    int e = blockIdx.x * blockDim.x + threadIdx.x;
    if (e < NE) {
        int d = ei[NE + e];
        int p = atomicAdd(&g_cursor[d], 1);
        g_src_sorted[p] = ei[e];
    }
}

// ---------------- GEMM1: g_h = (x @ W_gcn) * dinv[row] ----------------------
// BM=64, K=128, N=128. 256 thr, micro-tile 4 rows x 8 cols (4 col-pairs).
// Inner loop uses fma.rn.f32x2: 16 FFMA2 per k-iter (was 32 FFMA).
__global__ void __launch_bounds__(256) k_gemm1(const float* __restrict__ x,
                                               const float* __restrict__ Wg) {
    extern __shared__ float sm[];
    float* As = sm;                 // 64*128
    float* Ws = sm + 64 * F;        // 128*128
    int tid = threadIdx.x;
    #pragma unroll
    for (int it = 0; it < 16; it++) {
        int idx = it * 256 + tid;
        ((float4*)Ws)[idx] = ((const float4*)Wg)[idx];
    }
    int row0 = blockIdx.x * 64;
    #pragma unroll
    for (int it = 0; it < 8; it++) {
        int idx = it * 256 + tid;
        int r = idx >> 5, c4 = idx & 31;
        float4 v = make_float4(0.f, 0.f, 0.f, 0.f);
        if (row0 + r < NN) v = ((const float4*)(x + (size_t)(row0 + r) * F))[c4];
        ((float4*)(As + r * F))[c4] = v;
    }
    __syncthreads();

    int ty = tid >> 4, tx = tid & 15;
    u64 acc[4][4];                  // 4 rows x 4 column-pairs (8 cols)
    #pragma unroll
    for (int i = 0; i < 4; i++)
        #pragma unroll
        for (int j = 0; j < 4; j++) acc[i][j] = 0ULL;

    #pragma unroll 4
    for (int k = 0; k < F; k++) {
        u64 ad[4];
        #pragma unroll
        for (int i = 0; i < 4; i++) {
            float a = As[(ty * 4 + i) * F + k];
            ad[i] = pack2(a, a);
        }
        ulonglong2 bA = *(const ulonglong2*)&Ws[k * F + tx * 4];
        ulonglong2 bB = *(const ulonglong2*)&Ws[k * F + 64 + tx * 4];
        #pragma unroll
        for (int i = 0; i < 4; i++) {
            acc[i][0] = ffma2(ad[i], bA.x, acc[i][0]);
            acc[i][1] = ffma2(ad[i], bA.y, acc[i][1]);
            acc[i][2] = ffma2(ad[i], bB.x, acc[i][2]);
            acc[i][3] = ffma2(ad[i], bB.y, acc[i][3]);
        }
    }
    #pragma unroll
    for (int i = 0; i < 4; i++) {
        int r = row0 + ty * 4 + i;
        if (r < NN) {
            float di = g_dinv[r];
            u64 d2 = pack2(di, di);
            ulonglong2 o0, o1;
            o0.x = fmul2(acc[i][0], d2); o0.y = fmul2(acc[i][1], d2);
            o1.x = fmul2(acc[i][2], d2); o1.y = fmul2(acc[i][3], d2);
            *(ulonglong2*)&g_h[(size_t)r * F + tx * 4]      = o0;
            *(ulonglong2*)&g_h[(size_t)r * F + 64 + tx * 4] = o1;
        }
    }
}

// ---------------- aggregation (gather-only, warp per node) + BN1 stats ------
__global__ void __launch_bounds__(256) k_agg(const float* __restrict__ bgcn) {
    __shared__ float ss[8][F];
    __shared__ float sq[8][F];
    int w = threadIdx.x >> 5, lane = threadIdx.x & 31;
    int node = blockIdx.x * 8 + w;          // 12500 blocks * 8 == NN exactly

    float di = g_dinv[node];
    float4 acc = ((const float4*)(g_h + (size_t)node * F))[lane];

    int rs = g_rowstart[node];
    int cn = g_cnt[node];
    int t = 0;
    for (; t + 4 <= cn; t += 4) {
        int s0 = g_src_sorted[rs + t];
        int s1 = g_src_sorted[rs + t + 1];
        int s2 = g_src_sorted[rs + t + 2];
        int s3 = g_src_sorted[rs + t + 3];
        float4 v0 = ((const float4*)(g_h + (size_t)s0 * F))[lane];
        float4 v1 = ((const float4*)(g_h + (size_t)s1 * F))[lane];
        float4 v2 = ((const float4*)(g_h + (size_t)s2 * F))[lane];
        float4 v3 = ((const float4*)(g_h + (size_t)s3 * F))[lane];
        acc.x += v0.x + v1.x + v2.x + v3.x;
        acc.y += v0.y + v1.y + v2.y + v3.y;
        acc.z += v0.z + v1.z + v2.z + v3.z;
        acc.w += v0.w + v1.w + v2.w + v3.w;
    }
    for (; t < cn; t++) {
        int s = g_src_sorted[rs + t];
        float4 v = ((const float4*)(g_h + (size_t)s * F))[lane];
        acc.x += v.x; acc.y += v.y; acc.z += v.z; acc.w += v.w;
    }
    float4 bb = ((const float4*)bgcn)[lane];
    acc.x = fmaf(di, acc.x, bb.x);
    acc.y = fmaf(di, acc.y, bb.y);
    acc.z = fmaf(di, acc.z, bb.z);
    acc.w = fmaf(di, acc.w, bb.w);
    ((float4*)(g_agg + (size_t)node * F))[lane] = acc;

    int c = lane * 4;
    ss[w][c] = acc.x; ss[w][c + 1] = acc.y; ss[w][c + 2] = acc.z; ss[w][c + 3] = acc.w;
    sq[w][c] = acc.x * acc.x; sq[w][c + 1] = acc.y * acc.y;
    sq[w][c + 2] = acc.z * acc.z; sq[w][c + 3] = acc.w * acc.w;
    __syncthreads();
    if (threadIdx.x < F) {
        float s = 0.f, q = 0.f;
        #pragma unroll
        for (int i = 0; i < 8; i++) { s += ss[i][threadIdx.x]; q += sq[i][threadIdx.x]; }
        atomicAdd(&g_cs1[threadIdx.x], s);
        atomicAdd(&g_cq1[threadIdx.x], q);
    }
}

// ---- GEMM2: t1 = relu(bn1(agg)) @ W1 + b1, fused BN2 stats -----------------
// BM=64, K=128, N=64. 256 thr, micro 4x4 (2 col-pairs). FFMA2 inner loop.
__global__ void __launch_bounds__(256) k_gemm2(const float* __restrict__ gamma,
                                               const float* __restrict__ beta,
                                               const float* __restrict__ W1,
                                               const float* __restrict__ b1) {
    extern __shared__ float sm[];
    float* As = sm;                // 64*128
    float* Ws = As + 64 * F;       // 128*64
    float* sc = Ws + F * G;        // 128
    float* sh = sc + F;            // 128
    int tid = threadIdx.x;

    if (tid < F) {
        float mean = g_cs1[tid] * (1.f / NN);
        float var  = g_cq1[tid] * (1.f / NN) - mean * mean;
        float r    = rsqrtf(var + BN_EPS);
        float s    = r * gamma[tid];
        sc[tid] = s;
        sh[tid] = beta[tid] - mean * s;
    }
    #pragma unroll
    for (int it = 0; it < 8; it++) {
        int idx = it * 256 + tid;
        ((float4*)Ws)[idx] = ((const float4*)W1)[idx];
    }
    __syncthreads();

    int row0 = blockIdx.x * 64;
    #pragma unroll
    for (int it = 0; it < 8; it++) {
        int idx = it * 256 + tid;
        int r = idx >> 5, c4 = idx & 31;
        float4 v = make_float4(0.f, 0.f, 0.f, 0.f);
        if (row0 + r < NN) {
            float4 a = ((const float4*)(g_agg + (size_t)(row0 + r) * F))[c4];
            int c = c4 * 4;
            v.x = fmaxf(0.f, fmaf(a.x, sc[c],     sh[c]));
            v.y = fmaxf(0.f, fmaf(a.y, sc[c + 1], sh[c + 1]));
            v.z = fmaxf(0.f, fmaf(a.z, sc[c + 2], sh[c + 2]));
            v.w = fmaxf(0.f, fmaf(a.w, sc[c + 3], sh[c + 3]));
        }
        ((float4*)(As + r * F))[c4] = v;
    }
    __syncthreads();

    int ty = tid >> 4, tx = tid & 15;
    u64 acc[4][2];
    #pragma unroll
    for (int i = 0; i < 4; i++) { acc[i][0] = 0ULL; acc[i][1] = 0ULL; }

    #pragma unroll 4
    for (int k = 0; k < F; k++) {
        u64 ad[4];
        #pragma unroll
        for (int i = 0; i < 4; i++) {
            float a = As[(ty * 4 + i) * F + k];
            ad[i] = pack2(a, a);
        }
        ulonglong2 b = *(const ulonglong2*)&Ws[k * G + tx * 4];
        #pragma unroll
        for (int i = 0; i < 4; i++) {
            acc[i][0] = ffma2(ad[i], b.x, acc[i][0]);
            acc[i][1] = ffma2(ad[i], b.y, acc[i][1]);
        }
    }

    ulonglong2 bb = ((const ulonglong2*)b1)[tx];
    float ps[4] = {0.f, 0.f, 0.f, 0.f};
    float pq[4] = {0.f, 0.f, 0.f, 0.f};
    #pragma unroll
    for (int i = 0; i < 4; i++) {
        int r = row0 + ty * 4 + i;
        if (r < NN) {
            ulonglong2 o;
            o.x = fadd2(acc[i][0], bb.x);
            o.y = fadd2(acc[i][1], bb.y);
            *(ulonglong2*)&g_t1[(size_t)r * G + tx * 4] = o;
            float v0, v1, v2, v3;
            unpack2(o.x, v0, v1);
            unpack2(o.y, v2, v3);
            ps[0] += v0; ps[1] += v1; ps[2] += v2; ps[3] += v3;
            pq[0] += v0 * v0; pq[1] += v1 * v1;
            pq[2] += v2 * v2; pq[3] += v3 * v3;
        }
    }
    // block-reduce BN2 stats (reuse smem)
    __syncthreads();
    float* red = sm;               // 16*64
    #pragma unroll
    for (int j = 0; j < 4; j++) red[ty * G + tx * 4 + j] = ps[j];
    __syncthreads();
    if (tid < G) {
        float s = 0.f;
        #pragma unroll
        for (int i = 0; i < 16; i++) s += red[i * G + tid];
        atomicAdd(&g_cs2[tid], s);
    }
    __syncthreads();
    #pragma unroll
    for (int j = 0; j < 4; j++) red[ty * G + tx * 4 + j] = pq[j];
    __syncthreads();
    if (tid < G) {
        float q = 0.f;
        #pragma unroll
        for (int i = 0; i < 16; i++) q += red[i * G + tid];
        atomicAdd(&g_cq2[tid], q);
    }
}

// ---- GEMM3: out = relu(bn2(t1)) @ W2 + b2 ----------------------------------
__global__ void __launch_bounds__(256) k_gemm3(const float* __restrict__ gamma,
                                               const float* __restrict__ beta,
                                               const float* __restrict__ W2,
                                               const float* __restrict__ b2,
                                               float* __restrict__ out) {
    __shared__ float As[64 * G];
    __shared__ float Ws[G * G];
    __shared__ float sc[G];
    __shared__ float sh[G];
    int tid = threadIdx.x;

    if (tid < G) {
        float mean = g_cs2[tid] * (1.f / NN);
        float var  = g_cq2[tid] * (1.f / NN) - mean * mean;
        float r    = rsqrtf(var + BN_EPS);
        float s    = r * gamma[tid];
        sc[tid] = s;
        sh[tid] = beta[tid] - mean * s;
    }
    #pragma unroll
    for (int it = 0; it < 4; it++) {
        int idx = it * 256 + tid;
        ((float4*)Ws)[idx] = ((const float4*)W2)[idx];
    }
    __syncthreads();

    int row0 = blockIdx.x * 64;
    #pragma unroll
    for (int it = 0; it < 4; it++) {
        int idx = it * 256 + tid;
        int r = idx >> 4, c4 = idx & 15;
        float4 v = make_float4(0.f, 0.f, 0.f, 0.f);
        if (row0 + r < NN) {
            float4 a = ((const float4*)(g_t1 + (size_t)(row0 + r) * G))[c4];
            int c = c4 * 4;
            v.x = fmaxf(0.f, fmaf(a.x, sc[c],     sh[c]));
            v.y = fmaxf(0.f, fmaf(a.y, sc[c + 1], sh[c + 1]));
            v.z = fmaxf(0.f, fmaf(a.z, sc[c + 2], sh[c + 2]));
            v.w = fmaxf(0.f, fmaf(a.w, sc[c + 3], sh[c + 3]));
        }
        ((float4*)(As + r * G))[c4] = v;
    }
    __syncthreads();

    int ty = tid >> 4, tx = tid & 15;
    u64 acc[4][2];
    #pragma unroll
    for (int i = 0; i < 4; i++) { acc[i][0] = 0ULL; acc[i][1] = 0ULL; }

    #pragma unroll 4
    for (int k = 0; k < G; k++) {
        u64 ad[4];
        #pragma unroll
        for (int i = 0; i < 4; i++) {
            float a = As[(ty * 4 + i) * G + k];
            ad[i] = pack2(a, a);
        }
        ulonglong2 b = *(const ulonglong2*)&Ws[k * G + tx * 4];
        #pragma unroll
        for (int i = 0; i < 4; i++) {
            acc[i][0] = ffma2(ad[i], b.x, acc[i][0]);
            acc[i][1] = ffma2(ad[i], b.y, acc[i][1]);
        }
    }

    ulonglong2 bb = ((const ulonglong2*)b2)[tx];
    #pragma unroll
    for (int i = 0; i < 4; i++) {
        int r = row0 + ty * 4 + i;
        if (r < NN) {
            ulonglong2 o;
            o.x = fadd2(acc[i][0], bb.x);
            o.y = fadd2(acc[i][1], bb.y);
            *(ulonglong2*)&out[(size_t)r * G + tx * 4] = o;
        }
    }
}

// ---------------- host ------------------------------------------------------
extern "C" void kernel_launch(void* const* d_in, const int* in_sizes, int n_in,
                              void* d_out, int out_size) {
    const float* x   = (const float*)d_in[0];
    const int*   ei  = (const int*)  d_in[1];
    const float* Wg  = (const float*)d_in[2];
    const float* bg  = (const float*)d_in[3];
    const float* g1  = (const float*)d_in[4];
    const float* be1 = (const float*)d_in[5];
    const float* W1  = (const float*)d_in[6];
    const float* b1  = (const float*)d_in[7];
    const float* g2  = (const float*)d_in[8];
    const float* be2 = (const float*)d_in[9];
    const float* W2  = (const float*)d_in[10];
    const float* b2  = (const float*)d_in[11];
    float* out = (float*)d_out;

    cudaFuncSetAttribute(k_gemm1, cudaFuncAttributeMaxDynamicSharedMemorySize,
                         (64 * F + F * F) * (int)sizeof(float));
    cudaFuncSetAttribute(k_gemm2, cudaFuncAttributeMaxDynamicSharedMemorySize,
                         (64 * F + F * G + 2 * F) * (int)sizeof(float));

    int nblk_scan = (NN + SCAN_B - 1) / SCAN_B;   // 196
    int gemm_blocks = (NN + 63) / 64;             // 1563

    k_init  <<<(NN + 255) / 256, 256>>>();
    k_count <<<(NE + 255) / 256, 256>>>(ei);
    k_scan1 <<<nblk_scan, SCAN_B>>>();
    k_scan2 <<<1, 256>>>(nblk_scan);
    k_scan3 <<<(NN + 255) / 256, 256>>>();
    k_bucket<<<(NE + 255) / 256, 256>>>(ei);
    k_gemm1 <<<gemm_blocks, 256, (64 * F + F * F) * sizeof(float)>>>(x, Wg);
    k_agg   <<<NN / 8, 256>>>(bg);
    k_gemm2 <<<gemm_blocks, 256, (64 * F + F * G + 2 * F) * sizeof(float)>>>(g1, be1, W1, b1);
    k_gemm3 <<<gemm_blocks, 256>>>(g2, be2, W2, b2, out);
}